// round 15
// baseline (speedup 1.0000x reference)
#include <cuda_runtime.h>
#include <math.h>

#define NB 8192
#define PITCH 65
#define TPB 256
#define SWEEPS_MAX 12
#define SWEEPS_SMALL 12
#define SMEM_BYTES (3 * 64 * PITCH * 4)
#define FULLM 0xffffffffu
#define ROT_TH 1e-10f

__device__ float g_Msum[4096];
__device__ float g_Ssum[4096];
__device__ float g_c[4096];
__device__ float g_cinv[4096];
__device__ float g_sinv[4096];
__device__ float g_Y[(size_t)NB * 4096];   // cinv X cinv scratch
__device__ float g_W[(size_t)NB * 4096];   // final Jacobi columns
__device__ float g_g[(size_t)NB * 64];     // per-column log coefficients

// C = A * B, all 64x64 in shared with row pitch PITCH. 256 threads, 4x4 tile each.
__device__ __forceinline__ void mm64(const float* __restrict__ Ao,
                                     const float* __restrict__ Bo,
                                     float* __restrict__ Co, int tid) {
    const int i0 = (tid >> 4) << 2;
    const int j0 = (tid & 15) << 2;
    float acc[4][4];
#pragma unroll
    for (int r = 0; r < 4; ++r)
#pragma unroll
        for (int c = 0; c < 4; ++c) acc[r][c] = 0.f;
#pragma unroll 4
    for (int k = 0; k < 64; ++k) {
        float a0 = Ao[(i0 + 0) * PITCH + k];
        float a1 = Ao[(i0 + 1) * PITCH + k];
        float a2 = Ao[(i0 + 2) * PITCH + k];
        float a3 = Ao[(i0 + 3) * PITCH + k];
        float b0 = Bo[k * PITCH + j0 + 0];
        float b1 = Bo[k * PITCH + j0 + 1];
        float b2 = Bo[k * PITCH + j0 + 2];
        float b3 = Bo[k * PITCH + j0 + 3];
        acc[0][0] += a0 * b0; acc[0][1] += a0 * b1; acc[0][2] += a0 * b2; acc[0][3] += a0 * b3;
        acc[1][0] += a1 * b0; acc[1][1] += a1 * b1; acc[1][2] += a1 * b2; acc[1][3] += a1 * b3;
        acc[2][0] += a2 * b0; acc[2][1] += a2 * b1; acc[2][2] += a2 * b2; acc[2][3] += a2 * b3;
        acc[3][0] += a3 * b0; acc[3][1] += a3 * b1; acc[3][2] += a3 * b2; acc[3][3] += a3 * b3;
    }
#pragma unroll
    for (int r = 0; r < 4; ++r)
#pragma unroll
        for (int c = 0; c < 4; ++c) Co[(i0 + r) * PITCH + j0 + c] = acc[r][c];
}

// Two-sided cyclic Jacobi in shared (used only for the single-matrix solves).
__device__ void jacobi64(float* __restrict__ A, float* __restrict__ V,
                         int tid, int sweeps) {
    __shared__ int   Pp[32], Pq[32];
    __shared__ float Pc[32], Ps[32];
    for (int t = tid; t < 64 * PITCH; t += TPB) V[t] = 0.f;
    __syncthreads();
    if (tid < 64) V[tid * PITCH + tid] = 1.f;
    __syncthreads();

    for (int sw = 0; sw < sweeps; ++sw) {
        for (int r = 0; r < 63; ++r) {
            if (tid < 32) {
                int p, q;
                if (tid == 0) { p = 63; q = r; }
                else {
                    p = (r + tid) % 63;
                    q = (r + 63 - tid) % 63;
                }
                if (p > q) { int tt = p; p = q; q = tt; }
                float apq = A[p * PITCH + q];
                float c = 1.f, s = 0.f;
                if (fabsf(apq) > 1e-36f) {
                    float app = A[p * PITCH + p];
                    float aqq = A[q * PITCH + q];
                    float th = 0.5f * (aqq - app) / apq;
                    float t2 = copysignf(1.f, th) / (fabsf(th) + sqrtf(1.f + th * th));
                    c = rsqrtf(1.f + t2 * t2);
                    s = t2 * c;
                }
                Pp[tid] = p; Pq[tid] = q; Pc[tid] = c; Ps[tid] = s;
            }
            __syncthreads();
#pragma unroll 2
            for (int t = tid; t < 2048; t += TPB) {
                int k = t >> 6, j = t & 63;
                int p = Pp[k], q = Pq[k];
                float c = Pc[k], s = Ps[k];
                float ap = A[p * PITCH + j], aq = A[q * PITCH + j];
                A[p * PITCH + j] = c * ap - s * aq;
                A[q * PITCH + j] = s * ap + c * aq;
            }
            __syncthreads();
#pragma unroll 2
            for (int t = tid; t < 2048; t += TPB) {
                int k = t >> 6, i = t & 63;
                int p = Pp[k], q = Pq[k];
                float c = Pc[k], s = Ps[k];
                float ap = A[i * PITCH + p], aq = A[i * PITCH + q];
                A[i * PITCH + p] = c * ap - s * aq;
                A[i * PITCH + q] = s * ap + c * aq;
                float vp = V[i * PITCH + p], vq = V[i * PITCH + q];
                V[i * PITCH + p] = c * vp - s * vq;
                V[i * PITCH + q] = s * vp + c * vq;
            }
            __syncthreads();
        }
    }
}

// acc += V * diag(lam) * V^T, per-thread 4x4 tile
__device__ __forceinline__ void recon_accum(const float* __restrict__ V,
                                            const float* __restrict__ lam,
                                            float acc[4][4], int tid) {
    const int i0 = (tid >> 4) << 2;
    const int j0 = (tid & 15) << 2;
#pragma unroll 4
    for (int k = 0; k < 64; ++k) {
        float l = lam[k];
        float a0 = V[(i0 + 0) * PITCH + k] * l;
        float a1 = V[(i0 + 1) * PITCH + k] * l;
        float a2 = V[(i0 + 2) * PITCH + k] * l;
        float a3 = V[(i0 + 3) * PITCH + k] * l;
        float b0 = V[(j0 + 0) * PITCH + k];
        float b1 = V[(j0 + 1) * PITCH + k];
        float b2 = V[(j0 + 2) * PITCH + k];
        float b3 = V[(j0 + 3) * PITCH + k];
        acc[0][0] += a0 * b0; acc[0][1] += a0 * b1; acc[0][2] += a0 * b2; acc[0][3] += a0 * b3;
        acc[1][0] += a1 * b0; acc[1][1] += a1 * b1; acc[1][2] += a1 * b2; acc[1][3] += a1 * b3;
        acc[2][0] += a2 * b0; acc[2][1] += a2 * b1; acc[2][2] += a2 * b2; acc[2][3] += a2 * b3;
        acc[3][0] += a3 * b0; acc[3][1] += a3 * b1; acc[3][2] += a3 * b2; acc[3][3] += a3 * b3;
    }
}

__device__ __forceinline__ void recon_to_global(const float* __restrict__ V,
                                                const float* __restrict__ lam,
                                                float* __restrict__ out, int tid) {
    float acc[4][4];
#pragma unroll
    for (int r = 0; r < 4; ++r)
#pragma unroll
        for (int c = 0; c < 4; ++c) acc[r][c] = 0.f;
    recon_accum(V, lam, acc, tid);
    const int i0 = (tid >> 4) << 2;
    const int j0 = (tid & 15) << 2;
#pragma unroll
    for (int r = 0; r < 4; ++r)
#pragma unroll
        for (int c = 0; c < 4; ++c) out[(i0 + r) * 64 + j0 + c] = acc[r][c];
}

__global__ void k_init() {
    int t = blockIdx.x * 1024 + threadIdx.x;
    if (t < 4096) g_Msum[t] = 0.f;
    else if (t < 8192) g_Ssum[t - 4096] = 0.f;
}

__global__ void __launch_bounds__(TPB) k_mean(const float* __restrict__ x) {
    int b0 = blockIdx.x * 32;
    float acc[16];
#pragma unroll
    for (int u = 0; u < 16; ++u) acc[u] = 0.f;
    for (int b = 0; b < 32; ++b) {
        const float* m = x + (size_t)(b0 + b) * 4096;
#pragma unroll
        for (int u = 0; u < 16; ++u) acc[u] += m[threadIdx.x + 256 * u];
    }
#pragma unroll
    for (int u = 0; u < 16; ++u) atomicAdd(&g_Msum[threadIdx.x + 256 * u], acc[u]);
}

// Single block: eigh(mean) -> c = M^{1/2}, cinv = M^{-1/2}
__global__ void __launch_bounds__(TPB) k_center1() {
    extern __shared__ float sm[];
    float* A = sm;
    float* V = sm + 64 * PITCH;
    __shared__ float lam[64], fl[64];
    int tid = threadIdx.x;
    for (int t = tid; t < 4096; t += TPB)
        A[(t >> 6) * PITCH + (t & 63)] = g_Msum[t] * (1.f / NB);
    __syncthreads();
    jacobi64(A, V, tid, SWEEPS_SMALL);
    if (tid < 64) lam[tid] = fmaxf(A[tid * PITCH + tid], 1e-12f);
    __syncthreads();
    if (tid < 64) fl[tid] = sqrtf(lam[tid]);
    __syncthreads();
    recon_to_global(V, fl, g_c, tid);
    __syncthreads();
    if (tid < 64) fl[tid] = rsqrtf(lam[tid]);
    __syncthreads();
    recon_to_global(V, fl, g_cinv, tid);
}

// Y_b = cinv * X_b * cinv, symmetrized, to global scratch
__global__ void __launch_bounds__(TPB) k_sandwich(const float* __restrict__ x) {
    extern __shared__ float sm[];
    float* X  = sm;
    float* T  = sm + 64 * PITCH;
    float* CI = sm + 2 * 64 * PITCH;
    int tid = threadIdx.x;
    size_t base = (size_t)blockIdx.x * 4096;
    for (int t = tid; t < 4096; t += TPB) {
        CI[(t >> 6) * PITCH + (t & 63)] = g_cinv[t];
        X [(t >> 6) * PITCH + (t & 63)] = x[base + t];
    }
    __syncthreads();
    mm64(CI, X, T, tid);             // T = cinv * X
    __syncthreads();
    mm64(T, CI, X, tid);             // X := cinv * X * cinv
    __syncthreads();
    for (int t = tid; t < 4096; t += TPB) {
        int i = t >> 6, j = t & 63;
        g_Y[base + t] = 0.5f * (X[i * PITCH + j] + X[j * PITCH + i]);
    }
}

// One-sided Jacobi, one warp per matrix, 2 register columns per lane.
// Odd-even (Luk-Park) ordering with position swap. Rotation is unconditional
// (identity rotation c=1,s=0 performs the position swap); convergence tracked
// by a per-lane flag, checked once per sweep with a single __any_sync.
// launch_bounds(128,3): cap regs ~170 -> 12 warps/SM (3 per SMSP) for latency hiding.
__global__ void __launch_bounds__(128, 3) k_jacobi1s() {
    const int lane = threadIdx.x & 31;
    const int warp = threadIdx.x >> 5;
    const int b = blockIdx.x * 4 + warp;
    const float* Yb = g_Y + (size_t)b * 4096;

    float A[64], B[64];
#pragma unroll
    for (int i = 0; i < 16; ++i) {
        float4 v = ((const float4*)(Yb + (size_t)(2 * lane) * 64))[i];
        A[4 * i] = v.x; A[4 * i + 1] = v.y; A[4 * i + 2] = v.z; A[4 * i + 3] = v.w;
        float4 w = ((const float4*)(Yb + (size_t)(2 * lane + 1) * 64))[i];
        B[4 * i] = w.x; B[4 * i + 1] = w.y; B[4 * i + 2] = w.z; B[4 * i + 3] = w.w;
    }

    const bool valid = (lane < 31);
    float nA = 0.f, nB = 0.f;

    for (int sw = 0; sw < SWEEPS_MAX; ++sw) {
        // refresh norms (kills incremental drift)
        {
            float a0 = 0.f, a1 = 0.f, a2 = 0.f, a3 = 0.f;
            float c0 = 0.f, c1 = 0.f, c2 = 0.f, c3 = 0.f;
#pragma unroll
            for (int i = 0; i < 64; i += 4) {
                a0 += A[i] * A[i];         a1 += A[i + 1] * A[i + 1];
                a2 += A[i + 2] * A[i + 2]; a3 += A[i + 3] * A[i + 3];
                c0 += B[i] * B[i];         c1 += B[i + 1] * B[i + 1];
                c2 += B[i + 2] * B[i + 2]; c3 += B[i + 3] * B[i + 3];
            }
            nA = (a0 + a1) + (a2 + a3);
            nB = (c0 + c1) + (c2 + c3);
        }
        bool rotated = false;
        for (int rr = 0; rr < 32; ++rr) {
            // ---- even round: pair (A, B) within lane ----
            {
                float d0 = 0.f, d1 = 0.f, d2 = 0.f, d3 = 0.f;
#pragma unroll
                for (int i = 0; i < 64; i += 4) {
                    d0 += A[i] * B[i];
                    d1 += A[i + 1] * B[i + 1];
                    d2 += A[i + 2] * B[i + 2];
                    d3 += A[i + 3] * B[i + 3];
                }
                float apq = (d0 + d1) + (d2 + d3);
                bool rot = (apq * apq > ROT_TH * nA * nB) && (fabsf(apq) > 1e-36f);
                rotated |= rot;
                float c = 1.f, s = 0.f, t = 0.f;
                if (rot) {
                    float th = 0.5f * (nB - nA) / apq;
                    t = copysignf(1.f, th) / (fabsf(th) + sqrtf(1.f + th * th));
                    c = rsqrtf(1.f + t * t);
                    s = t * c;
                }
                // rotate + swap positions: A := q' , B := p'
#pragma unroll
                for (int i = 0; i < 64; ++i) {
                    float a = A[i], e = B[i];
                    A[i] = s * a + c * e;
                    B[i] = c * a - s * e;
                }
                float nAn = nB + t * apq;   // aqq'
                float nBn = nA - t * apq;   // app'
                nA = nAn; nB = nBn;
            }
            // ---- odd round: pair (B, next lane's A); swap across lanes ----
            {
                float nP = __shfl_down_sync(FULLM, nA, 1);
                float d0 = 0.f, d1 = 0.f, d2 = 0.f, d3 = 0.f;
#pragma unroll
                for (int i = 0; i < 64; i += 4) {
                    float p0 = __shfl_down_sync(FULLM, A[i], 1);
                    float p1 = __shfl_down_sync(FULLM, A[i + 1], 1);
                    float p2 = __shfl_down_sync(FULLM, A[i + 2], 1);
                    float p3 = __shfl_down_sync(FULLM, A[i + 3], 1);
                    d0 += B[i] * p0;
                    d1 += B[i + 1] * p1;
                    d2 += B[i + 2] * p2;
                    d3 += B[i + 3] * p3;
                }
                float apq = (d0 + d1) + (d2 + d3);
                bool rot = valid && (apq * apq > ROT_TH * nB * nP) && (fabsf(apq) > 1e-36f);
                rotated |= rot;
                float c = 1.f, s = 0.f, t = 0.f;
                if (rot) {
                    float th = 0.5f * (nP - nB) / apq;
                    t = copysignf(1.f, th) / (fabsf(th) + sqrtf(1.f + th * th));
                    c = rsqrtf(1.f + t * t);
                    s = t * c;
                }
                // rotate + exchange: pos2l+1 := q'(prot), pos2l+2 := p'(brot)
#pragma unroll
                for (int i = 0; i < 64; ++i) {
                    float p = __shfl_down_sync(FULLM, A[i], 1);
                    float e = B[i];
                    float brot = c * e - s * p;   // p' -> pos 2l+2 (next lane A)
                    float prot = s * e + c * p;   // q' -> pos 2l+1 (this lane B)
                    float up = __shfl_up_sync(FULLM, brot, 1);
                    if (valid) B[i] = prot;
                    if (lane > 0) A[i] = up;
                }
                float sendn = nB - t * apq;       // app' for pos 2l+2
                float nup = __shfl_up_sync(FULLM, sendn, 1);
                if (valid) nB = nP + t * apq;     // aqq' for pos 2l+1
                if (lane > 0) nA = nup;
            }
        }
        if (!__any_sync(FULLM, rotated)) break;   // fully converged sweep
    }

    // exact final norms -> lambda = ||w||^2, g = 0.5*log(||w||^2)/||w||^2
    {
        float a0 = 0.f, a1 = 0.f, a2 = 0.f, a3 = 0.f;
        float c0 = 0.f, c1 = 0.f, c2 = 0.f, c3 = 0.f;
#pragma unroll
        for (int i = 0; i < 64; i += 4) {
            a0 += A[i] * A[i];         a1 += A[i + 1] * A[i + 1];
            a2 += A[i + 2] * A[i + 2]; a3 += A[i + 3] * A[i + 3];
            c0 += B[i] * B[i];         c1 += B[i + 1] * B[i + 1];
            c2 += B[i + 2] * B[i + 2]; c3 += B[i + 3] * B[i + 3];
        }
        nA = fmaxf((a0 + a1) + (a2 + a3), 1e-24f);
        nB = fmaxf((c0 + c1) + (c2 + c3), 1e-24f);
    }
    float gA = 0.5f * logf(nA) / nA;
    float gB = 0.5f * logf(nB) / nB;

    float* Wa = g_W + (size_t)b * 4096 + (size_t)(2 * lane) * 64;
    float* Wb = g_W + (size_t)b * 4096 + (size_t)(2 * lane + 1) * 64;
#pragma unroll
    for (int i = 0; i < 16; ++i) {
        ((float4*)Wa)[i] = make_float4(A[4 * i], A[4 * i + 1], A[4 * i + 2], A[4 * i + 3]);
        ((float4*)Wb)[i] = make_float4(B[4 * i], B[4 * i + 1], B[4 * i + 2], B[4 * i + 3]);
    }
    g_g[(size_t)b * 64 + 2 * lane] = gA;
    g_g[(size_t)b * 64 + 2 * lane + 1] = gB;
}

// Ssum += sum_b W_b diag(g_b) W_b^T
__global__ void __launch_bounds__(TPB) k_reduce() {
    extern __shared__ float sm[];
    float* W = sm;
    __shared__ float lam[64];
    int tid = threadIdx.x;
    float acc[4][4];
#pragma unroll
    for (int r = 0; r < 4; ++r)
#pragma unroll
        for (int c = 0; c < 4; ++c) acc[r][c] = 0.f;

    for (int b = blockIdx.x; b < NB; b += gridDim.x) {
        size_t base = (size_t)b * 4096;
        for (int t = tid; t < 4096; t += TPB)
            W[(t & 63) * PITCH + (t >> 6)] = g_W[base + t];
        if (tid < 64) lam[tid] = g_g[(size_t)b * 64 + tid];
        __syncthreads();
        recon_accum(W, lam, acc, tid);
        __syncthreads();
    }
    const int i0 = (tid >> 4) << 2;
    const int j0 = (tid & 15) << 2;
#pragma unroll
    for (int r = 0; r < 4; ++r)
#pragma unroll
        for (int c = 0; c < 4; ++c)
            atomicAdd(&g_Ssum[(i0 + r) * 64 + j0 + c], acc[r][c]);
}

// Single block: Sbar = Ssum/NB; m_new = c expm(Sbar) c; sinv = m_new^{-1/2}
__global__ void __launch_bounds__(TPB) k_center2() {
    extern __shared__ float sm[];
    float* A = sm;
    float* V = sm + 64 * PITCH;
    float* C = sm + 2 * 64 * PITCH;
    __shared__ float lam[64];
    int tid = threadIdx.x;
    for (int t = tid; t < 4096; t += TPB)
        A[(t >> 6) * PITCH + (t & 63)] = g_Ssum[t] * (1.f / NB);
    __syncthreads();
    jacobi64(A, V, tid, SWEEPS_SMALL);
    if (tid < 64) lam[tid] = expf(A[tid * PITCH + tid]);
    __syncthreads();
    {
        float acc[4][4];
#pragma unroll
        for (int r = 0; r < 4; ++r)
#pragma unroll
            for (int c = 0; c < 4; ++c) acc[r][c] = 0.f;
        recon_accum(V, lam, acc, tid);
        const int i0 = (tid >> 4) << 2;
        const int j0 = (tid & 15) << 2;
#pragma unroll
        for (int r = 0; r < 4; ++r)
#pragma unroll
            for (int c = 0; c < 4; ++c) A[(i0 + r) * PITCH + j0 + c] = acc[r][c];
    }
    for (int t = tid; t < 4096; t += TPB)
        C[(t >> 6) * PITCH + (t & 63)] = g_c[t];
    __syncthreads();
    mm64(C, A, V, tid);
    __syncthreads();
    mm64(V, C, A, tid);
    __syncthreads();
    jacobi64(A, V, tid, SWEEPS_SMALL);
    if (tid < 64) lam[tid] = rsqrtf(fmaxf(A[tid * PITCH + tid], 1e-12f));
    __syncthreads();
    recon_to_global(V, lam, g_sinv, tid);
}

// out_b = sinv * X_b * sinv
__global__ void __launch_bounds__(TPB) k_out(const float* __restrict__ x,
                                             float* __restrict__ out) {
    extern __shared__ float sm[];
    float* S = sm;
    float* X = sm + 64 * PITCH;
    float* T = sm + 2 * 64 * PITCH;
    int tid = threadIdx.x;
    size_t base = (size_t)blockIdx.x * 4096;
    for (int t = tid; t < 4096; t += TPB) {
        S[(t >> 6) * PITCH + (t & 63)] = g_sinv[t];
        X[(t >> 6) * PITCH + (t & 63)] = x[base + t];
    }
    __syncthreads();
    mm64(S, X, T, tid);
    __syncthreads();
    const int i0 = (tid >> 4) << 2;
    const int j0 = (tid & 15) << 2;
    float acc[4][4];
#pragma unroll
    for (int r = 0; r < 4; ++r)
#pragma unroll
        for (int c = 0; c < 4; ++c) acc[r][c] = 0.f;
#pragma unroll 4
    for (int k = 0; k < 64; ++k) {
        float a0 = T[(i0 + 0) * PITCH + k];
        float a1 = T[(i0 + 1) * PITCH + k];
        float a2 = T[(i0 + 2) * PITCH + k];
        float a3 = T[(i0 + 3) * PITCH + k];
        float b0 = S[k * PITCH + j0 + 0];
        float b1 = S[k * PITCH + j0 + 1];
        float b2 = S[k * PITCH + j0 + 2];
        float b3 = S[k * PITCH + j0 + 3];
        acc[0][0] += a0 * b0; acc[0][1] += a0 * b1; acc[0][2] += a0 * b2; acc[0][3] += a0 * b3;
        acc[1][0] += a1 * b0; acc[1][1] += a1 * b1; acc[1][2] += a1 * b2; acc[1][3] += a1 * b3;
        acc[2][0] += a2 * b0; acc[2][1] += a2 * b1; acc[2][2] += a2 * b2; acc[2][3] += a2 * b3;
        acc[3][0] += a3 * b0; acc[3][1] += a3 * b1; acc[3][2] += a3 * b2; acc[3][3] += a3 * b3;
    }
#pragma unroll
    for (int r = 0; r < 4; ++r)
#pragma unroll
        for (int c = 0; c < 4; ++c)
            out[base + (i0 + r) * 64 + j0 + c] = acc[r][c];
}

extern "C" void kernel_launch(void* const* d_in, const int* in_sizes, int n_in,
                              void* d_out, int out_size) {
    const float* x = (const float*)d_in[0];
    float* out = (float*)d_out;

    cudaFuncSetAttribute(k_center1,  cudaFuncAttributeMaxDynamicSharedMemorySize, SMEM_BYTES);
    cudaFuncSetAttribute(k_sandwich, cudaFuncAttributeMaxDynamicSharedMemorySize, SMEM_BYTES);
    cudaFuncSetAttribute(k_center2,  cudaFuncAttributeMaxDynamicSharedMemorySize, SMEM_BYTES);
    cudaFuncSetAttribute(k_out,      cudaFuncAttributeMaxDynamicSharedMemorySize, SMEM_BYTES);

    k_init<<<8, 1024>>>();
    k_mean<<<256, TPB>>>(x);
    k_center1<<<1, TPB, SMEM_BYTES>>>();
    k_sandwich<<<NB, TPB, SMEM_BYTES>>>(x);
    k_jacobi1s<<<NB / 4, 128>>>();
    k_reduce<<<256, TPB, 64 * PITCH * 4>>>();
    k_center2<<<1, TPB, SMEM_BYTES>>>();
    k_out<<<NB, TPB, SMEM_BYTES>>>(x, out);
}

// round 16
// speedup vs baseline: 1.0108x; 1.0108x over previous
#include <cuda_runtime.h>
#include <math.h>

#define NB 8192
#define PITCH 65
#define TPB 256
#define SWEEPS_MAX 12
#define SWEEPS_SMALL 12
#define SMEM_BYTES (3 * 64 * PITCH * 4)
#define FULLM 0xffffffffu
#define ROT_TH 1e-10f

__device__ float g_Msum[4096];
__device__ float g_Ssum[4096];
__device__ float g_c[4096];
__device__ float g_cinv[4096];
__device__ float g_sinv[4096];
__device__ float g_Y[(size_t)NB * 4096];   // cinv X cinv scratch
__device__ float g_W[(size_t)NB * 4096];   // final Jacobi columns
__device__ float g_g[(size_t)NB * 64];     // per-column log coefficients

// ---------- packed f32x2 helpers (Blackwell dual-fp32 path) ----------
__device__ __forceinline__ unsigned long long ffma2(unsigned long long a,
                                                    unsigned long long b,
                                                    unsigned long long c) {
    unsigned long long r;
    asm("fma.rn.f32x2 %0, %1, %2, %3;" : "=l"(r) : "l"(a), "l"(b), "l"(c));
    return r;
}
__device__ __forceinline__ unsigned long long fmul2(unsigned long long a,
                                                    unsigned long long b) {
    unsigned long long r;
    asm("mul.rn.f32x2 %0, %1, %2;" : "=l"(r) : "l"(a), "l"(b));
    return r;
}
__device__ __forceinline__ unsigned long long fpack2(float x, float y) {
    unsigned long long r;
    asm("mov.b64 %0, {%1, %2};" : "=l"(r) : "f"(x), "f"(y));
    return r;
}
__device__ __forceinline__ float2 funpack2(unsigned long long a) {
    float x, y;
    asm("mov.b64 {%0, %1}, %2;" : "=f"(x), "=f"(y) : "l"(a));
    return make_float2(x, y);
}
__device__ __forceinline__ float nrm2_packed(const unsigned long long* X) {
    unsigned long long q0 = 0ull, q1 = 0ull, q2 = 0ull, q3 = 0ull;
#pragma unroll
    for (int i = 0; i < 32; i += 4) {
        q0 = ffma2(X[i], X[i], q0);
        q1 = ffma2(X[i + 1], X[i + 1], q1);
        q2 = ffma2(X[i + 2], X[i + 2], q2);
        q3 = ffma2(X[i + 3], X[i + 3], q3);
    }
    float2 f0 = funpack2(q0), f1 = funpack2(q1), f2 = funpack2(q2), f3 = funpack2(q3);
    return ((f0.x + f0.y) + (f1.x + f1.y)) + ((f2.x + f2.y) + (f3.x + f3.y));
}
__device__ __forceinline__ float dot_packed(const unsigned long long* X,
                                            const unsigned long long* Y) {
    unsigned long long q0 = 0ull, q1 = 0ull, q2 = 0ull, q3 = 0ull;
#pragma unroll
    for (int i = 0; i < 32; i += 4) {
        q0 = ffma2(X[i], Y[i], q0);
        q1 = ffma2(X[i + 1], Y[i + 1], q1);
        q2 = ffma2(X[i + 2], Y[i + 2], q2);
        q3 = ffma2(X[i + 3], Y[i + 3], q3);
    }
    float2 f0 = funpack2(q0), f1 = funpack2(q1), f2 = funpack2(q2), f3 = funpack2(q3);
    return ((f0.x + f0.y) + (f1.x + f1.y)) + ((f2.x + f2.y) + (f3.x + f3.y));
}

// C = A * B, all 64x64 in shared with row pitch PITCH. 256 threads, 4x4 tile each.
__device__ __forceinline__ void mm64(const float* __restrict__ Ao,
                                     const float* __restrict__ Bo,
                                     float* __restrict__ Co, int tid) {
    const int i0 = (tid >> 4) << 2;
    const int j0 = (tid & 15) << 2;
    float acc[4][4];
#pragma unroll
    for (int r = 0; r < 4; ++r)
#pragma unroll
        for (int c = 0; c < 4; ++c) acc[r][c] = 0.f;
#pragma unroll 4
    for (int k = 0; k < 64; ++k) {
        float a0 = Ao[(i0 + 0) * PITCH + k];
        float a1 = Ao[(i0 + 1) * PITCH + k];
        float a2 = Ao[(i0 + 2) * PITCH + k];
        float a3 = Ao[(i0 + 3) * PITCH + k];
        float b0 = Bo[k * PITCH + j0 + 0];
        float b1 = Bo[k * PITCH + j0 + 1];
        float b2 = Bo[k * PITCH + j0 + 2];
        float b3 = Bo[k * PITCH + j0 + 3];
        acc[0][0] += a0 * b0; acc[0][1] += a0 * b1; acc[0][2] += a0 * b2; acc[0][3] += a0 * b3;
        acc[1][0] += a1 * b0; acc[1][1] += a1 * b1; acc[1][2] += a1 * b2; acc[1][3] += a1 * b3;
        acc[2][0] += a2 * b0; acc[2][1] += a2 * b1; acc[2][2] += a2 * b2; acc[2][3] += a2 * b3;
        acc[3][0] += a3 * b0; acc[3][1] += a3 * b1; acc[3][2] += a3 * b2; acc[3][3] += a3 * b3;
    }
#pragma unroll
    for (int r = 0; r < 4; ++r)
#pragma unroll
        for (int c = 0; c < 4; ++c) Co[(i0 + r) * PITCH + j0 + c] = acc[r][c];
}

// Two-sided cyclic Jacobi in shared (used only for the single-matrix solves).
__device__ void jacobi64(float* __restrict__ A, float* __restrict__ V,
                         int tid, int sweeps) {
    __shared__ int   Pp[32], Pq[32];
    __shared__ float Pc[32], Ps[32];
    for (int t = tid; t < 64 * PITCH; t += TPB) V[t] = 0.f;
    __syncthreads();
    if (tid < 64) V[tid * PITCH + tid] = 1.f;
    __syncthreads();

    for (int sw = 0; sw < sweeps; ++sw) {
        for (int r = 0; r < 63; ++r) {
            if (tid < 32) {
                int p, q;
                if (tid == 0) { p = 63; q = r; }
                else {
                    p = (r + tid) % 63;
                    q = (r + 63 - tid) % 63;
                }
                if (p > q) { int tt = p; p = q; q = tt; }
                float apq = A[p * PITCH + q];
                float c = 1.f, s = 0.f;
                if (fabsf(apq) > 1e-36f) {
                    float app = A[p * PITCH + p];
                    float aqq = A[q * PITCH + q];
                    float th = 0.5f * (aqq - app) / apq;
                    float t2 = copysignf(1.f, th) / (fabsf(th) + sqrtf(1.f + th * th));
                    c = rsqrtf(1.f + t2 * t2);
                    s = t2 * c;
                }
                Pp[tid] = p; Pq[tid] = q; Pc[tid] = c; Ps[tid] = s;
            }
            __syncthreads();
#pragma unroll 2
            for (int t = tid; t < 2048; t += TPB) {
                int k = t >> 6, j = t & 63;
                int p = Pp[k], q = Pq[k];
                float c = Pc[k], s = Ps[k];
                float ap = A[p * PITCH + j], aq = A[q * PITCH + j];
                A[p * PITCH + j] = c * ap - s * aq;
                A[q * PITCH + j] = s * ap + c * aq;
            }
            __syncthreads();
#pragma unroll 2
            for (int t = tid; t < 2048; t += TPB) {
                int k = t >> 6, i = t & 63;
                int p = Pp[k], q = Pq[k];
                float c = Pc[k], s = Ps[k];
                float ap = A[i * PITCH + p], aq = A[i * PITCH + q];
                A[i * PITCH + p] = c * ap - s * aq;
                A[i * PITCH + q] = s * ap + c * aq;
                float vp = V[i * PITCH + p], vq = V[i * PITCH + q];
                V[i * PITCH + p] = c * vp - s * vq;
                V[i * PITCH + q] = s * vp + c * vq;
            }
            __syncthreads();
        }
    }
}

// acc += V * diag(lam) * V^T, per-thread 4x4 tile
__device__ __forceinline__ void recon_accum(const float* __restrict__ V,
                                            const float* __restrict__ lam,
                                            float acc[4][4], int tid) {
    const int i0 = (tid >> 4) << 2;
    const int j0 = (tid & 15) << 2;
#pragma unroll 4
    for (int k = 0; k < 64; ++k) {
        float l = lam[k];
        float a0 = V[(i0 + 0) * PITCH + k] * l;
        float a1 = V[(i0 + 1) * PITCH + k] * l;
        float a2 = V[(i0 + 2) * PITCH + k] * l;
        float a3 = V[(i0 + 3) * PITCH + k] * l;
        float b0 = V[(j0 + 0) * PITCH + k];
        float b1 = V[(j0 + 1) * PITCH + k];
        float b2 = V[(j0 + 2) * PITCH + k];
        float b3 = V[(j0 + 3) * PITCH + k];
        acc[0][0] += a0 * b0; acc[0][1] += a0 * b1; acc[0][2] += a0 * b2; acc[0][3] += a0 * b3;
        acc[1][0] += a1 * b0; acc[1][1] += a1 * b1; acc[1][2] += a1 * b2; acc[1][3] += a1 * b3;
        acc[2][0] += a2 * b0; acc[2][1] += a2 * b1; acc[2][2] += a2 * b2; acc[2][3] += a2 * b3;
        acc[3][0] += a3 * b0; acc[3][1] += a3 * b1; acc[3][2] += a3 * b2; acc[3][3] += a3 * b3;
    }
}

__device__ __forceinline__ void recon_to_global(const float* __restrict__ V,
                                                const float* __restrict__ lam,
                                                float* __restrict__ out, int tid) {
    float acc[4][4];
#pragma unroll
    for (int r = 0; r < 4; ++r)
#pragma unroll
        for (int c = 0; c < 4; ++c) acc[r][c] = 0.f;
    recon_accum(V, lam, acc, tid);
    const int i0 = (tid >> 4) << 2;
    const int j0 = (tid & 15) << 2;
#pragma unroll
    for (int r = 0; r < 4; ++r)
#pragma unroll
        for (int c = 0; c < 4; ++c) out[(i0 + r) * 64 + j0 + c] = acc[r][c];
}

__global__ void k_init() {
    int t = blockIdx.x * 1024 + threadIdx.x;
    if (t < 4096) g_Msum[t] = 0.f;
    else if (t < 8192) g_Ssum[t - 4096] = 0.f;
}

__global__ void __launch_bounds__(TPB) k_mean(const float* __restrict__ x) {
    int b0 = blockIdx.x * 32;
    float acc[16];
#pragma unroll
    for (int u = 0; u < 16; ++u) acc[u] = 0.f;
    for (int b = 0; b < 32; ++b) {
        const float* m = x + (size_t)(b0 + b) * 4096;
#pragma unroll
        for (int u = 0; u < 16; ++u) acc[u] += m[threadIdx.x + 256 * u];
    }
#pragma unroll
    for (int u = 0; u < 16; ++u) atomicAdd(&g_Msum[threadIdx.x + 256 * u], acc[u]);
}

// Single block: eigh(mean) -> c = M^{1/2}, cinv = M^{-1/2}
__global__ void __launch_bounds__(TPB) k_center1() {
    extern __shared__ float sm[];
    float* A = sm;
    float* V = sm + 64 * PITCH;
    __shared__ float lam[64], fl[64];
    int tid = threadIdx.x;
    for (int t = tid; t < 4096; t += TPB)
        A[(t >> 6) * PITCH + (t & 63)] = g_Msum[t] * (1.f / NB);
    __syncthreads();
    jacobi64(A, V, tid, SWEEPS_SMALL);
    if (tid < 64) lam[tid] = fmaxf(A[tid * PITCH + tid], 1e-12f);
    __syncthreads();
    if (tid < 64) fl[tid] = sqrtf(lam[tid]);
    __syncthreads();
    recon_to_global(V, fl, g_c, tid);
    __syncthreads();
    if (tid < 64) fl[tid] = rsqrtf(lam[tid]);
    __syncthreads();
    recon_to_global(V, fl, g_cinv, tid);
}

// Y_b = cinv * X_b * cinv, symmetrized, to global scratch
__global__ void __launch_bounds__(TPB) k_sandwich(const float* __restrict__ x) {
    extern __shared__ float sm[];
    float* X  = sm;
    float* T  = sm + 64 * PITCH;
    float* CI = sm + 2 * 64 * PITCH;
    int tid = threadIdx.x;
    size_t base = (size_t)blockIdx.x * 4096;
    for (int t = tid; t < 4096; t += TPB) {
        CI[(t >> 6) * PITCH + (t & 63)] = g_cinv[t];
        X [(t >> 6) * PITCH + (t & 63)] = x[base + t];
    }
    __syncthreads();
    mm64(CI, X, T, tid);             // T = cinv * X
    __syncthreads();
    mm64(T, CI, X, tid);             // X := cinv * X * cinv
    __syncthreads();
    for (int t = tid; t < 4096; t += TPB) {
        int i = t >> 6, j = t & 63;
        g_Y[base + t] = 0.5f * (X[i * PITCH + j] + X[j * PITCH + i]);
    }
}

// One-sided Jacobi, one warp per matrix, 2 packed register columns per lane.
// Odd-even (Luk-Park) ordering with position swap; rotation is unconditional
// (identity rotation c=1,s=0 performs the position swap). Packed f32x2 math.
__global__ void __launch_bounds__(128, 2) k_jacobi1s() {
    const int lane = threadIdx.x & 31;
    const int warp = threadIdx.x >> 5;
    const int b = blockIdx.x * 4 + warp;
    const unsigned long long* Yb =
        (const unsigned long long*)(g_Y + (size_t)b * 4096);

    unsigned long long A2[32], B2[32];
#pragma unroll
    for (int i = 0; i < 32; ++i) {
        A2[i] = Yb[lane * 64 + i];        // column 2*lane
        B2[i] = Yb[lane * 64 + 32 + i];   // column 2*lane+1
    }

    const bool valid = (lane < 31);
    float nA = 0.f, nB = 0.f;

    for (int sw = 0; sw < SWEEPS_MAX; ++sw) {
        nA = nrm2_packed(A2);
        nB = nrm2_packed(B2);
        bool rotated = false;
        for (int rr = 0; rr < 32; ++rr) {
            // ---- even round: pair (A, B) within lane ----
            {
                float apq = dot_packed(A2, B2);
                bool rot = (apq * apq > ROT_TH * nA * nB) && (fabsf(apq) > 1e-36f);
                rotated |= rot;
                float c = 1.f, s = 0.f, t = 0.f;
                if (rot) {
                    float th = 0.5f * (nB - nA) / apq;
                    t = copysignf(1.f, th) / (fabsf(th) + sqrtf(1.f + th * th));
                    c = rsqrtf(1.f + t * t);
                    s = t * c;
                }
                unsigned long long c2 = fpack2(c, c);
                unsigned long long s2 = fpack2(s, s);
                unsigned long long ns2 = fpack2(-s, -s);
                // rotate + swap positions: A := q' = s*a + c*e ; B := p' = c*a - s*e
#pragma unroll
                for (int i = 0; i < 32; ++i) {
                    unsigned long long a = A2[i], e = B2[i];
                    A2[i] = ffma2(s2, a, fmul2(c2, e));
                    B2[i] = ffma2(ns2, e, fmul2(c2, a));
                }
                float nAn = nB + t * apq;   // aqq'
                float nBn = nA - t * apq;   // app'
                nA = nAn; nB = nBn;
            }
            // ---- odd round: pair (B, next lane's A); swap across lanes ----
            {
                float nP = __shfl_down_sync(FULLM, nA, 1);
                unsigned long long q0 = 0ull, q1 = 0ull, q2 = 0ull, q3 = 0ull;
#pragma unroll
                for (int i = 0; i < 32; i += 4) {
                    unsigned long long p0 = __shfl_down_sync(FULLM, A2[i], 1);
                    unsigned long long p1 = __shfl_down_sync(FULLM, A2[i + 1], 1);
                    unsigned long long p2 = __shfl_down_sync(FULLM, A2[i + 2], 1);
                    unsigned long long p3 = __shfl_down_sync(FULLM, A2[i + 3], 1);
                    q0 = ffma2(B2[i], p0, q0);
                    q1 = ffma2(B2[i + 1], p1, q1);
                    q2 = ffma2(B2[i + 2], p2, q2);
                    q3 = ffma2(B2[i + 3], p3, q3);
                }
                float2 f0 = funpack2(q0), f1 = funpack2(q1),
                       f2 = funpack2(q2), f3 = funpack2(q3);
                float apq = ((f0.x + f0.y) + (f1.x + f1.y)) +
                            ((f2.x + f2.y) + (f3.x + f3.y));
                bool rot = valid && (apq * apq > ROT_TH * nB * nP) && (fabsf(apq) > 1e-36f);
                rotated |= rot;
                float c = 1.f, s = 0.f, t = 0.f;
                if (rot) {
                    float th = 0.5f * (nP - nB) / apq;
                    t = copysignf(1.f, th) / (fabsf(th) + sqrtf(1.f + th * th));
                    c = rsqrtf(1.f + t * t);
                    s = t * c;
                }
                unsigned long long c2 = fpack2(c, c);
                unsigned long long s2 = fpack2(s, s);
                unsigned long long ns2 = fpack2(-s, -s);
                // rotate + exchange: pos2l+1 := q'(prot), pos2l+2 := p'(brot)
#pragma unroll
                for (int i = 0; i < 32; ++i) {
                    unsigned long long p = __shfl_down_sync(FULLM, A2[i], 1);
                    unsigned long long e = B2[i];
                    unsigned long long brot = ffma2(ns2, p, fmul2(c2, e)); // c*e - s*p
                    unsigned long long prot = ffma2(s2, e, fmul2(c2, p)); // s*e + c*p
                    unsigned long long up = __shfl_up_sync(FULLM, brot, 1);
                    if (valid) B2[i] = prot;
                    if (lane > 0) A2[i] = up;
                }
                float sendn = nB - t * apq;       // app' for pos 2l+2
                float nup = __shfl_up_sync(FULLM, sendn, 1);
                if (valid) nB = nP + t * apq;     // aqq' for pos 2l+1
                if (lane > 0) nA = nup;
            }
        }
        if (!__any_sync(FULLM, rotated)) break;   // fully converged sweep
    }

    // exact final norms -> lambda = ||w||^2, g = 0.5*log(||w||^2)/||w||^2
    nA = fmaxf(nrm2_packed(A2), 1e-24f);
    nB = fmaxf(nrm2_packed(B2), 1e-24f);
    float gA = 0.5f * logf(nA) / nA;
    float gB = 0.5f * logf(nB) / nB;

    unsigned long long* Wo = (unsigned long long*)(g_W + (size_t)b * 4096);
#pragma unroll
    for (int i = 0; i < 32; ++i) {
        Wo[lane * 64 + i] = A2[i];
        Wo[lane * 64 + 32 + i] = B2[i];
    }
    g_g[(size_t)b * 64 + 2 * lane] = gA;
    g_g[(size_t)b * 64 + 2 * lane + 1] = gB;
}

// Ssum += sum_b W_b diag(g_b) W_b^T
__global__ void __launch_bounds__(TPB) k_reduce() {
    extern __shared__ float sm[];
    float* W = sm;
    __shared__ float lam[64];
    int tid = threadIdx.x;
    float acc[4][4];
#pragma unroll
    for (int r = 0; r < 4; ++r)
#pragma unroll
        for (int c = 0; c < 4; ++c) acc[r][c] = 0.f;

    for (int b = blockIdx.x; b < NB; b += gridDim.x) {
        size_t base = (size_t)b * 4096;
        for (int t = tid; t < 4096; t += TPB)
            W[(t & 63) * PITCH + (t >> 6)] = g_W[base + t];
        if (tid < 64) lam[tid] = g_g[(size_t)b * 64 + tid];
        __syncthreads();
        recon_accum(W, lam, acc, tid);
        __syncthreads();
    }
    const int i0 = (tid >> 4) << 2;
    const int j0 = (tid & 15) << 2;
#pragma unroll
    for (int r = 0; r < 4; ++r)
#pragma unroll
        for (int c = 0; c < 4; ++c)
            atomicAdd(&g_Ssum[(i0 + r) * 64 + j0 + c], acc[r][c]);
}

// Single block: Sbar = Ssum/NB; m_new = c expm(Sbar) c; sinv = m_new^{-1/2}
__global__ void __launch_bounds__(TPB) k_center2() {
    extern __shared__ float sm[];
    float* A = sm;
    float* V = sm + 64 * PITCH;
    float* C = sm + 2 * 64 * PITCH;
    __shared__ float lam[64];
    int tid = threadIdx.x;
    for (int t = tid; t < 4096; t += TPB)
        A[(t >> 6) * PITCH + (t & 63)] = g_Ssum[t] * (1.f / NB);
    __syncthreads();
    jacobi64(A, V, tid, SWEEPS_SMALL);
    if (tid < 64) lam[tid] = expf(A[tid * PITCH + tid]);
    __syncthreads();
    {
        float acc[4][4];
#pragma unroll
        for (int r = 0; r < 4; ++r)
#pragma unroll
            for (int c = 0; c < 4; ++c) acc[r][c] = 0.f;
        recon_accum(V, lam, acc, tid);
        const int i0 = (tid >> 4) << 2;
        const int j0 = (tid & 15) << 2;
#pragma unroll
        for (int r = 0; r < 4; ++r)
#pragma unroll
            for (int c = 0; c < 4; ++c) A[(i0 + r) * PITCH + j0 + c] = acc[r][c];
    }
    for (int t = tid; t < 4096; t += TPB)
        C[(t >> 6) * PITCH + (t & 63)] = g_c[t];
    __syncthreads();
    mm64(C, A, V, tid);
    __syncthreads();
    mm64(V, C, A, tid);
    __syncthreads();
    jacobi64(A, V, tid, SWEEPS_SMALL);
    if (tid < 64) lam[tid] = rsqrtf(fmaxf(A[tid * PITCH + tid], 1e-12f));
    __syncthreads();
    recon_to_global(V, lam, g_sinv, tid);
}

// out_b = sinv * X_b * sinv
__global__ void __launch_bounds__(TPB) k_out(const float* __restrict__ x,
                                             float* __restrict__ out) {
    extern __shared__ float sm[];
    float* S = sm;
    float* X = sm + 64 * PITCH;
    float* T = sm + 2 * 64 * PITCH;
    int tid = threadIdx.x;
    size_t base = (size_t)blockIdx.x * 4096;
    for (int t = tid; t < 4096; t += TPB) {
        S[(t >> 6) * PITCH + (t & 63)] = g_sinv[t];
        X[(t >> 6) * PITCH + (t & 63)] = x[base + t];
    }
    __syncthreads();
    mm64(S, X, T, tid);
    __syncthreads();
    const int i0 = (tid >> 4) << 2;
    const int j0 = (tid & 15) << 2;
    float acc[4][4];
#pragma unroll
    for (int r = 0; r < 4; ++r)
#pragma unroll
        for (int c = 0; c < 4; ++c) acc[r][c] = 0.f;
#pragma unroll 4
    for (int k = 0; k < 64; ++k) {
        float a0 = T[(i0 + 0) * PITCH + k];
        float a1 = T[(i0 + 1) * PITCH + k];
        float a2 = T[(i0 + 2) * PITCH + k];
        float a3 = T[(i0 + 3) * PITCH + k];
        float b0 = S[k * PITCH + j0 + 0];
        float b1 = S[k * PITCH + j0 + 1];
        float b2 = S[k * PITCH + j0 + 2];
        float b3 = S[k * PITCH + j0 + 3];
        acc[0][0] += a0 * b0; acc[0][1] += a0 * b1; acc[0][2] += a0 * b2; acc[0][3] += a0 * b3;
        acc[1][0] += a1 * b0; acc[1][1] += a1 * b1; acc[1][2] += a1 * b2; acc[1][3] += a1 * b3;
        acc[2][0] += a2 * b0; acc[2][1] += a2 * b1; acc[2][2] += a2 * b2; acc[2][3] += a2 * b3;
        acc[3][0] += a3 * b0; acc[3][1] += a3 * b1; acc[3][2] += a3 * b2; acc[3][3] += a3 * b3;
    }
#pragma unroll
    for (int r = 0; r < 4; ++r)
#pragma unroll
        for (int c = 0; c < 4; ++c)
            out[base + (i0 + r) * 64 + j0 + c] = acc[r][c];
}

extern "C" void kernel_launch(void* const* d_in, const int* in_sizes, int n_in,
                              void* d_out, int out_size) {
    const float* x = (const float*)d_in[0];
    float* out = (float*)d_out;

    cudaFuncSetAttribute(k_center1,  cudaFuncAttributeMaxDynamicSharedMemorySize, SMEM_BYTES);
    cudaFuncSetAttribute(k_sandwich, cudaFuncAttributeMaxDynamicSharedMemorySize, SMEM_BYTES);
    cudaFuncSetAttribute(k_center2,  cudaFuncAttributeMaxDynamicSharedMemorySize, SMEM_BYTES);
    cudaFuncSetAttribute(k_out,      cudaFuncAttributeMaxDynamicSharedMemorySize, SMEM_BYTES);

    k_init<<<8, 1024>>>();
    k_mean<<<256, TPB>>>(x);
    k_center1<<<1, TPB, SMEM_BYTES>>>();
    k_sandwich<<<NB, TPB, SMEM_BYTES>>>(x);
    k_jacobi1s<<<NB / 4, 128>>>();
    k_reduce<<<256, TPB, 64 * PITCH * 4>>>();
    k_center2<<<1, TPB, SMEM_BYTES>>>();
    k_out<<<NB, TPB, SMEM_BYTES>>>(x, out);
}